// round 7
// baseline (speedup 1.0000x reference)
#include <cuda_runtime.h>

#define HEADS 4
#define NEG_SLOPE 0.2f

static const int N_CAP  = 100000;
static const int EN_CAP = 1700000;
static const int SCAN_CHUNK = 512;

typedef unsigned long long ull;

// ---------------- scratch (static device globals; no allocation) -------------
__device__ float g_h  [N_CAP * 64];   // transformed features h = in @ W   [N, F]
__device__ float g_o  [N_CAP * 64];   // aggregated output (next layer in) [N, F]
__device__ float g_als[N_CAP * HEADS];
__device__ float g_ald[N_CAP * HEADS];
__device__ int   g_src[EN_CAP];
__device__ int   g_dst[EN_CAP];
__device__ int   g_csr_src[EN_CAP];
__device__ int   g_deg[N_CAP];
__device__ int   g_inc[N_CAP];
__device__ int   g_off[N_CAP + 1];
__device__ int   g_cursor[N_CAP];
__device__ int   g_bsum[256];
__device__ int   g_boff[256];
__device__ float g_psum[64 * 8];
__device__ float g_pcnt[64];
__device__ int   g_is64;

// ---------------- helpers ----------------------------------------------------
__device__ __forceinline__ float lrelu(float x) { return x > 0.f ? x : NEG_SLOPE * x; }

// packed fp32x2 FMA (Blackwell; PTX-only — ptxas won't auto-fuse)
__device__ __forceinline__ void ffma2(ull& d, ull a, ull b) {
    asm("fma.rn.f32x2 %0, %1, %2, %0;" : "+l"(d) : "l"(a), "l"(b));
}
__device__ __forceinline__ float unpack_sum(ull v) {
    float lo, hi;
    asm("mov.b64 {%0,%1}, %2;" : "=f"(lo), "=f"(hi) : "l"(v));
    return lo + hi;
}

// ---------------- index-width detection --------------------------------------
__global__ void k_detect(const unsigned* __restrict__ w, int pairs) {
    __shared__ int any;
    if (threadIdx.x == 0) any = 0;
    __syncthreads();
    int lim = pairs < 4096 ? pairs : 4096;
    int local = 0;
    for (int i = threadIdx.x; i < lim; i += blockDim.x)
        if (w[2 * i + 1] != 0u) local = 1;
    if (local) atomicExch(&any, 1);
    __syncthreads();
    if (threadIdx.x == 0) g_is64 = (any == 0) ? 1 : 0;
}

// ---------------- zero transient state ---------------------------------------
__global__ void k_zero(int N) {
    int i = blockIdx.x * blockDim.x + threadIdx.x;
    if (i < N) { g_deg[i] = 0; g_cursor[i] = 0; }
    if (i < 512) g_psum[i] = 0.f;
    if (i < 64)  g_pcnt[i] = 0.f;
}

// ---------------- decode edges + dst histogram --------------------------------
__global__ void k_hist(const void* __restrict__ ei, int E, int N) {
    int i = blockIdx.x * blockDim.x + threadIdx.x;
    int EN = E + N;
    if (i >= EN) return;
    int s, d;
    if (i < E) {
        if (g_is64) {
            const long long* p = (const long long*)ei;
            s = (int)p[i]; d = (int)p[E + i];
        } else {
            const int* p = (const int*)ei;
            s = p[i]; d = p[E + i];
        }
    } else {             // self-loops appended (PyG GATConv behavior)
        s = d = i - E;
    }
    g_src[i] = s;
    g_dst[i] = d;
    atomicAdd(&g_deg[d], 1);
}

// ---------------- 3-phase exclusive scan of g_deg -> g_off --------------------
__global__ __launch_bounds__(SCAN_CHUNK) void k_scanA(int N) {
    __shared__ int sh[SCAN_CHUNK];
    int i = blockIdx.x * SCAN_CHUNK + threadIdx.x;
    int v = (i < N) ? g_deg[i] : 0;
    sh[threadIdx.x] = v;
    __syncthreads();
    for (int off = 1; off < SCAN_CHUNK; off <<= 1) {
        int t = (threadIdx.x >= off) ? sh[threadIdx.x - off] : 0;
        __syncthreads();
        sh[threadIdx.x] += t;
        __syncthreads();
    }
    if (i < N) g_inc[i] = sh[threadIdx.x];
    if (threadIdx.x == SCAN_CHUNK - 1) g_bsum[blockIdx.x] = sh[SCAN_CHUNK - 1];
}

__global__ __launch_bounds__(256) void k_scanB(int NB) {
    __shared__ int sh[256];
    int t = threadIdx.x;
    int v = (t < NB) ? g_bsum[t] : 0;
    sh[t] = v;
    __syncthreads();
    for (int off = 1; off < 256; off <<= 1) {
        int tv = (t >= off) ? sh[t - off] : 0;
        __syncthreads();
        sh[t] += tv;
        __syncthreads();
    }
    if (t < NB) g_boff[t] = sh[t] - v;   // exclusive
}

__global__ void k_scanC(int N) {
    int i = blockIdx.x * blockDim.x + threadIdx.x;
    if (i >= N) return;
    int b = i / SCAN_CHUNK;
    int inc = g_inc[i] + g_boff[b];
    g_off[i] = inc - g_deg[i];
    if (i == N - 1) g_off[N] = inc;
}

// ---------------- scatter edges into CSR order --------------------------------
__global__ void k_csr_scatter(int EN) {
    int i = blockIdx.x * blockDim.x + threadIdx.x;
    if (i >= EN) return;
    int d = g_dst[i];
    int pos = g_off[d] + atomicAdd(&g_cursor[d], 1);
    g_csr_src[pos] = g_src[i];
}

// ---------------- GEMM (f32x2 packed) + fused attention-logit epilogue -------
// g_h = act(in [+bias]) @ W ; g_als/g_ald = per-head dot(h_row, a_src/a_dst).
// W staged TRANSPOSED in smem ([m][k], KT=K+2 pad) so (w_k, w_k+1) is one
// LDS.64; inputs read as natural (a_k, a_k+1) pairs. Mainloop = fma.rn.f32x2:
// half the FFMA and half the LDS instruction count vs scalar fp32.
template<int K, int M, int ROWS>
__global__ __launch_bounds__(256) void k_gemm(
    const float* __restrict__ in_ext, int use_int,
    const float* __restrict__ W, const float* __restrict__ bias,
    const float* __restrict__ a_src, const float* __restrict__ a_dst, int N)
{
    constexpr int CG  = M / 4;
    constexpr int RG  = 256 / CG;
    constexpr int RPT = ROWS / RG;
    constexpr int OC  = M / HEADS;
    constexpr int RED = (OC >= 4) ? OC / 4 : 1;
    constexpr int KT  = K + 2;            // even pad: 8B-aligned pairs, no bank walls
    extern __shared__ float smem[];
    float* sW  = smem;                    // [M][KT] transposed weights
    float* sIn = smem + M * KT;           // [ROWS][KT]

    const float* in = use_int ? g_o : in_ext;
    int r0 = blockIdx.x * ROWS;

    for (int i = threadIdx.x; i < K * M; i += 256) {
        int k = i / M, m = i - k * M;
        sW[m * KT + k] = W[i];
    }
    for (int i = threadIdx.x; i < ROWS * K; i += 256) {
        int r = i / K, k = i - r * K;
        int gr = r0 + r;
        float v = 0.f;
        if (gr < N) {
            v = in[gr * K + k];
            if (bias) { v += bias[k]; v = fmaxf(v, 0.f); }
        }
        sIn[r * KT + k] = v;
    }
    __syncthreads();

    int cg = threadIdx.x % CG;
    int rg = threadIdx.x / CG;
    const ull* sWv = (const ull*)sW;      // pair view; KT even -> indices exact

    ull acc2[RPT][4];
#pragma unroll
    for (int i = 0; i < RPT; i++)
#pragma unroll
        for (int c = 0; c < 4; c++) acc2[i][c] = 0ull;

#pragma unroll 4
    for (int k2 = 0; k2 < K / 2; k2++) {
        ull w0 = sWv[((cg * 4 + 0) * KT) / 2 + k2];
        ull w1 = sWv[((cg * 4 + 1) * KT) / 2 + k2];
        ull w2 = sWv[((cg * 4 + 2) * KT) / 2 + k2];
        ull w3 = sWv[((cg * 4 + 3) * KT) / 2 + k2];
#pragma unroll
        for (int i = 0; i < RPT; i++) {
            ull a2 = *(const ull*)&sIn[(rg * RPT + i) * KT + 2 * k2];
            ffma2(acc2[i][0], a2, w0);
            ffma2(acc2[i][1], a2, w1);
            ffma2(acc2[i][2], a2, w2);
            ffma2(acc2[i][3], a2, w3);
        }
    }

    float4 asv = *(const float4*)&a_src[cg * 4];
    float4 adv = *(const float4*)&a_dst[cg * 4];

#pragma unroll
    for (int i = 0; i < RPT; i++) {
        float a0 = unpack_sum(acc2[i][0]);
        float a1 = unpack_sum(acc2[i][1]);
        float a2 = unpack_sum(acc2[i][2]);
        float a3 = unpack_sum(acc2[i][3]);
        int gr = r0 + rg * RPT + i;
        bool ok = (gr < N);
        if (ok)
            *(float4*)&g_h[gr * M + cg * 4] = make_float4(a0, a1, a2, a3);
        if constexpr (OC >= 4) {
            float vs = a0*asv.x + a1*asv.y + a2*asv.z + a3*asv.w;
            float vd = a0*adv.x + a1*adv.y + a2*adv.z + a3*adv.w;
#pragma unroll
            for (int o = 1; o < RED; o <<= 1) {
                vs += __shfl_xor_sync(0xffffffffu, vs, o, 32);
                vd += __shfl_xor_sync(0xffffffffu, vd, o, 32);
            }
            if (ok && (cg % RED) == 0) {
                int head = cg / RED;
                g_als[gr * HEADS + head] = vs;
                g_ald[gr * HEADS + head] = vd;
            }
        } else {  // OC == 2: thread's 4 cols span 2 heads
            float vs0 = a0*asv.x + a1*asv.y;
            float vd0 = a0*adv.x + a1*adv.y;
            float vs1 = a2*asv.z + a3*asv.w;
            float vd1 = a2*adv.z + a3*adv.w;
            if (ok) {
                g_als[gr * HEADS + cg * 2 + 0] = vs0;
                g_ald[gr * HEADS + cg * 2 + 0] = vd0;
                g_als[gr * HEADS + cg * 2 + 1] = vs1;
                g_ald[gr * HEADS + cg * 2 + 1] = vd1;
            }
        }
    }
}

// ---------------- fused softmax + aggregation (CSR gather, no atomics) --------
// TPN = F/V threads per node. Per 8-edge batch: indices, logits, AND the 8
// feature vectors are all loaded before the FMA chain -> MLP 8 on the
// dominant L2-latency chain. Softmax shift skipped (shift-invariant, O(1)
// logits).
template<int OC>
__global__ __launch_bounds__(256) void k_agg(int N) {
    constexpr int F   = HEADS * OC;
    constexpr int V   = (OC >= 4) ? 4 : 2;
    constexpr int TPN = F / V;
    constexpr int LPH = OC / V;        // lanes per head
    constexpr int NPB = 256 / TPN;
    int node = blockIdx.x * NPB + threadIdx.x / TPN;
    if (node >= N) node = N - 1;       // clamp: duplicate compute, identical writes
    int t    = threadIdx.x % TPN;
    int head = t / LPH;

    int beg = g_off[node], end = g_off[node + 1];
    float ald_d = g_ald[node * HEADS + head];

    float acc[V];
#pragma unroll
    for (int v = 0; v < V; v++) acc[v] = 0.f;
    float ssum = 0.f;

    int p = beg;
    for (; p + 8 <= end; p += 8) {
        int ss[8];
#pragma unroll
        for (int j = 0; j < 8; j++) ss[j] = g_csr_src[p + j];
        float al[8];
#pragma unroll
        for (int j = 0; j < 8; j++) al[j] = g_als[ss[j] * HEADS + head];
        if constexpr (V == 4) {
            float4 hv[8];
#pragma unroll
            for (int j = 0; j < 8; j++)
                hv[j] = *(const float4*)&g_h[ss[j] * F + t * V];
#pragma unroll
            for (int j = 0; j < 8; j++) {
                float ex = __expf(lrelu(al[j] + ald_d));
                ssum += ex;
                acc[0] += ex * hv[j].x; acc[1] += ex * hv[j].y;
                acc[2] += ex * hv[j].z; acc[3] += ex * hv[j].w;
            }
        } else {
            float2 hv[8];
#pragma unroll
            for (int j = 0; j < 8; j++)
                hv[j] = *(const float2*)&g_h[ss[j] * F + t * V];
#pragma unroll
            for (int j = 0; j < 8; j++) {
                float ex = __expf(lrelu(al[j] + ald_d));
                ssum += ex;
                acc[0] += ex * hv[j].x; acc[1] += ex * hv[j].y;
            }
        }
    }
    for (; p < end; p++) {
        int s = g_csr_src[p];
        float ex = __expf(lrelu(g_als[s * HEADS + head] + ald_d));
        ssum += ex;
        const float* hp = &g_h[s * F + t * V];
        if constexpr (V == 4) {
            float4 hv = *(const float4*)hp;
            acc[0] += ex * hv.x; acc[1] += ex * hv.y;
            acc[2] += ex * hv.z; acc[3] += ex * hv.w;
        } else {
            float2 hv = *(const float2*)hp;
            acc[0] += ex * hv.x; acc[1] += ex * hv.y;
        }
    }

    float inv = 1.f / (ssum + 1e-16f);
    float* op = &g_o[node * F + t * V];
    if constexpr (V == 4)
        *(float4*)op = make_float4(acc[0] * inv, acc[1] * inv, acc[2] * inv, acc[3] * inv);
    else
        *(float2*)op = make_float2(acc[0] * inv, acc[1] * inv);
}

// ---------------- pooling + fc -----------------------------------------------
__global__ void k_pool(const void* __restrict__ batch,
                       const float* __restrict__ b4, int N) {
    int n = blockIdx.x * blockDim.x + threadIdx.x;
    if (n >= N) return;
    int g = g_is64 ? (int)((const long long*)batch)[n]
                   : ((const int*)batch)[n];
#pragma unroll
    for (int j = 0; j < 8; j++) {
        float v = fmaxf(g_o[n * 8 + j] + b4[j], 0.f);
        atomicAdd(&g_psum[g * 8 + j], v);
    }
    atomicAdd(&g_pcnt[b4 ? g : g], 1.f);
}

__global__ void k_fc(const float* __restrict__ Wfc,
                     const float* __restrict__ bfc, float* __restrict__ out) {
    int b = blockIdx.x, o = threadIdx.x;  // grid 64, block 32
    float c = fmaxf(g_pcnt[b], 1.f);
    float acc = bfc[o];
#pragma unroll
    for (int j = 0; j < 8; j++)
        acc += (g_psum[b * 8 + j] / c) * Wfc[j * 32 + o];
    out[b * 32 + o] = acc;
}

// ---------------- launch ------------------------------------------------------
extern "C" void kernel_launch(void* const* d_in, const int* in_sizes, int n_in,
                              void* d_out, int out_size) {
    const float* x    = (const float*)d_in[0];
    const void*  ei   = d_in[1];
    const void*  batch= d_in[2];
    const float* W1  = (const float*)d_in[3];
    const float* as1 = (const float*)d_in[4];
    const float* ad1 = (const float*)d_in[5];
    const float* b1  = (const float*)d_in[6];
    const float* W2  = (const float*)d_in[7];
    const float* as2 = (const float*)d_in[8];
    const float* ad2 = (const float*)d_in[9];
    const float* b2  = (const float*)d_in[10];
    const float* W3  = (const float*)d_in[11];
    const float* as3 = (const float*)d_in[12];
    const float* ad3 = (const float*)d_in[13];
    const float* b3  = (const float*)d_in[14];
    const float* W4  = (const float*)d_in[15];
    const float* as4 = (const float*)d_in[16];
    const float* ad4 = (const float*)d_in[17];
    const float* b4  = (const float*)d_in[18];
    const float* Wfc = (const float*)d_in[19];
    const float* bfc = (const float*)d_in[20];
    float* out = (float*)d_out;

    int N  = in_sizes[0] / 128;
    int E  = in_sizes[1] / 2;
    int EN = E + N;

    int nb = (N + 255) / 256;
    int eb = (EN + 255) / 256;
    int NB = (N + SCAN_CHUNK - 1) / SCAN_CHUNK;

    // dynamic smem sizes: (M + ROWS) * (K+2) floats
    const int S1 = (64 + 32)  * 130 * 4;   // 49920 B
    const int S2 = (32 + 128) * 66  * 4;   // 42240 B
    const int S3 = (16 + 256) * 34  * 4;   // 36992 B
    const int S4 = (8  + 512) * 18  * 4;   // 37440 B
    static int attr_done = 0;
    if (!attr_done) {
        cudaFuncSetAttribute(k_gemm<128, 64, 32>,
            cudaFuncAttributeMaxDynamicSharedMemorySize, S1);
        cudaFuncSetAttribute(k_gemm<64, 32, 128>,
            cudaFuncAttributeMaxDynamicSharedMemorySize, S2);
        cudaFuncSetAttribute(k_gemm<32, 16, 256>,
            cudaFuncAttributeMaxDynamicSharedMemorySize, S3);
        cudaFuncSetAttribute(k_gemm<16, 8, 512>,
            cudaFuncAttributeMaxDynamicSharedMemorySize, S4);
        attr_done = 1;
    }

    // ---- CSR build (once; reused by all 4 layers) ----
    k_detect<<<1, 256>>>((const unsigned*)ei, E);
    k_zero<<<nb, 256>>>(N);
    k_hist<<<eb, 256>>>(ei, E, N);
    k_scanA<<<NB, SCAN_CHUNK>>>(N);
    k_scanB<<<1, 256>>>(NB);
    k_scanC<<<nb, 256>>>(N);
    k_csr_scatter<<<eb, 256>>>(EN);

    // ---- layer 1 (in=x), F = 64 ----
    k_gemm<128, 64, 32><<<(N + 31) / 32, 256, S1>>>(x, 0, W1, nullptr, as1, ad1, N);
    k_agg<16><<<(N + 15) / 16, 256>>>(N);

    // ---- layer 2 (in = relu(g_o + b1)), F = 32 ----
    k_gemm<64, 32, 128><<<(N + 127) / 128, 256, S2>>>(nullptr, 1, W2, b1, as2, ad2, N);
    k_agg<8><<<(N + 31) / 32, 256>>>(N);

    // ---- layer 3, F = 16 ----
    k_gemm<32, 16, 256><<<(N + 255) / 256, 256, S3>>>(nullptr, 1, W3, b2, as3, ad3, N);
    k_agg<4><<<(N + 63) / 64, 256>>>(N);

    // ---- layer 4, F = 8 ----
    k_gemm<16, 8, 512><<<(N + 511) / 512, 256, S4>>>(nullptr, 1, W4, b3, as4, ad4, N);
    k_agg<2><<<(N + 63) / 64, 256>>>(N);

    // ---- global mean pool (relu(g_o + b4)) + fc ----
    k_pool<<<nb, 256>>>(batch, b4, N);
    k_fc<<<64, 32>>>(Wfc, bfc, out);
}

// round 8
// speedup vs baseline: 1.0653x; 1.0653x over previous
#include <cuda_runtime.h>

#define HEADS 4
#define NEG_SLOPE 0.2f

static const int N_CAP  = 100000;
static const int EN_CAP = 1700000;
static const int SCAN_CHUNK = 512;

// ---------------- scratch (static device globals; no allocation) -------------
__device__ float g_h  [N_CAP * 64];   // transformed features h = in @ W   [N, F]
__device__ float g_o  [N_CAP * 64];   // aggregated output (next layer in) [N, F]
__device__ float g_als[N_CAP * HEADS];
__device__ float g_ald[N_CAP * HEADS];
__device__ int   g_src[EN_CAP];
__device__ int   g_dst[EN_CAP];
__device__ int   g_csr_src[EN_CAP];
__device__ int   g_deg[N_CAP];
__device__ int   g_inc[N_CAP];
__device__ int   g_off[N_CAP + 1];
__device__ int   g_cursor[N_CAP];
__device__ int   g_bsum[256];
__device__ int   g_boff[256];
__device__ float g_psum[64 * 8];
__device__ float g_pcnt[64];
__device__ int   g_is64;

// ---------------- helpers ----------------------------------------------------
__device__ __forceinline__ float lrelu(float x) { return x > 0.f ? x : NEG_SLOPE * x; }

// ---------------- index-width detection --------------------------------------
__global__ void k_detect(const unsigned* __restrict__ w, int pairs) {
    __shared__ int any;
    if (threadIdx.x == 0) any = 0;
    __syncthreads();
    int lim = pairs < 4096 ? pairs : 4096;
    int local = 0;
    for (int i = threadIdx.x; i < lim; i += blockDim.x)
        if (w[2 * i + 1] != 0u) local = 1;
    if (local) atomicExch(&any, 1);
    __syncthreads();
    if (threadIdx.x == 0) g_is64 = (any == 0) ? 1 : 0;
}

// ---------------- zero transient state ---------------------------------------
__global__ void k_zero(int N) {
    int i = blockIdx.x * blockDim.x + threadIdx.x;
    if (i < N) { g_deg[i] = 0; g_cursor[i] = 0; }
    if (i < 512) g_psum[i] = 0.f;
    if (i < 64)  g_pcnt[i] = 0.f;
}

// ---------------- decode edges + dst histogram --------------------------------
__global__ void k_hist(const void* __restrict__ ei, int E, int N) {
    int i = blockIdx.x * blockDim.x + threadIdx.x;
    int EN = E + N;
    if (i >= EN) return;
    int s, d;
    if (i < E) {
        if (g_is64) {
            const long long* p = (const long long*)ei;
            s = (int)p[i]; d = (int)p[E + i];
        } else {
            const int* p = (const int*)ei;
            s = p[i]; d = p[E + i];
        }
    } else {             // self-loops appended (PyG GATConv behavior)
        s = d = i - E;
    }
    g_src[i] = s;
    g_dst[i] = d;
    atomicAdd(&g_deg[d], 1);
}

// ---------------- 3-phase exclusive scan of g_deg -> g_off --------------------
__global__ __launch_bounds__(SCAN_CHUNK) void k_scanA(int N) {
    __shared__ int sh[SCAN_CHUNK];
    int i = blockIdx.x * SCAN_CHUNK + threadIdx.x;
    int v = (i < N) ? g_deg[i] : 0;
    sh[threadIdx.x] = v;
    __syncthreads();
    for (int off = 1; off < SCAN_CHUNK; off <<= 1) {
        int t = (threadIdx.x >= off) ? sh[threadIdx.x - off] : 0;
        __syncthreads();
        sh[threadIdx.x] += t;
        __syncthreads();
    }
    if (i < N) g_inc[i] = sh[threadIdx.x];
    if (threadIdx.x == SCAN_CHUNK - 1) g_bsum[blockIdx.x] = sh[SCAN_CHUNK - 1];
}

__global__ __launch_bounds__(256) void k_scanB(int NB) {
    __shared__ int sh[256];
    int t = threadIdx.x;
    int v = (t < NB) ? g_bsum[t] : 0;
    sh[t] = v;
    __syncthreads();
    for (int off = 1; off < 256; off <<= 1) {
        int tv = (t >= off) ? sh[t - off] : 0;
        __syncthreads();
        sh[t] += tv;
        __syncthreads();
    }
    if (t < NB) g_boff[t] = sh[t] - v;   // exclusive
}

__global__ void k_scanC(int N) {
    int i = blockIdx.x * blockDim.x + threadIdx.x;
    if (i >= N) return;
    int b = i / SCAN_CHUNK;
    int inc = g_inc[i] + g_boff[b];
    g_off[i] = inc - g_deg[i];
    if (i == N - 1) g_off[N] = inc;
}

// ---------------- scatter edges into CSR order --------------------------------
__global__ void k_csr_scatter(int EN) {
    int i = blockIdx.x * blockDim.x + threadIdx.x;
    if (i >= EN) return;
    int d = g_dst[i];
    int pos = g_off[d] + atomicAdd(&g_cursor[d], 1);
    g_csr_src[pos] = g_src[i];
}

// ---------------- GEMM + fused attention-logit epilogue (round-6 proven) -----
// g_h = act(in [+bias]) @ W ; g_als/g_ald = per-head dot(h_row, a_src/a_dst).
template<int K, int M, int ROWS>
__global__ __launch_bounds__(256) void k_gemm(
    const float* __restrict__ in_ext, int use_int,
    const float* __restrict__ W, const float* __restrict__ bias,
    const float* __restrict__ a_src, const float* __restrict__ a_dst, int N)
{
    constexpr int CG  = M / 4;
    constexpr int RG  = 256 / CG;
    constexpr int RPT = ROWS / RG;
    constexpr int OC  = M / HEADS;
    constexpr int RED = (OC >= 4) ? OC / 4 : 1;
    constexpr int KP  = (K == 128) ? K : (K + 1);
    __shared__ float sW[K * M];
    __shared__ float sIn[ROWS * KP];

    const float* in = use_int ? g_o : in_ext;
    int r0 = blockIdx.x * ROWS;

    for (int i = threadIdx.x; i < K * M; i += 256) sW[i] = W[i];
    for (int i = threadIdx.x; i < ROWS * K; i += 256) {
        int r = i / K, k = i - r * K;
        int gr = r0 + r;
        float v = 0.f;
        if (gr < N) {
            v = in[gr * K + k];
            if (bias) { v += bias[k]; v = fmaxf(v, 0.f); }
        }
        sIn[r * KP + k] = v;
    }
    __syncthreads();

    int cg = threadIdx.x % CG;
    int rg = threadIdx.x / CG;
    float acc[RPT][4];
#pragma unroll
    for (int i = 0; i < RPT; i++)
        acc[i][0] = acc[i][1] = acc[i][2] = acc[i][3] = 0.f;

#pragma unroll 8
    for (int k = 0; k < K; k++) {
        float w0 = sW[k * M + cg * 4 + 0];
        float w1 = sW[k * M + cg * 4 + 1];
        float w2 = sW[k * M + cg * 4 + 2];
        float w3 = sW[k * M + cg * 4 + 3];
#pragma unroll
        for (int i = 0; i < RPT; i++) {
            float a = sIn[(rg * RPT + i) * KP + k];
            acc[i][0] += a * w0; acc[i][1] += a * w1;
            acc[i][2] += a * w2; acc[i][3] += a * w3;
        }
    }

    float4 asv = *(const float4*)&a_src[cg * 4];
    float4 adv = *(const float4*)&a_dst[cg * 4];

#pragma unroll
    for (int i = 0; i < RPT; i++) {
        int gr = r0 + rg * RPT + i;
        bool ok = (gr < N);
        if (ok) {
            float4 v = make_float4(acc[i][0], acc[i][1], acc[i][2], acc[i][3]);
            *(float4*)&g_h[gr * M + cg * 4] = v;
        }
        if constexpr (OC >= 4) {
            float vs = acc[i][0]*asv.x + acc[i][1]*asv.y + acc[i][2]*asv.z + acc[i][3]*asv.w;
            float vd = acc[i][0]*adv.x + acc[i][1]*adv.y + acc[i][2]*adv.z + acc[i][3]*adv.w;
#pragma unroll
            for (int o = 1; o < RED; o <<= 1) {
                vs += __shfl_xor_sync(0xffffffffu, vs, o, 32);
                vd += __shfl_xor_sync(0xffffffffu, vd, o, 32);
            }
            if (ok && (cg % RED) == 0) {
                int head = cg / RED;
                g_als[gr * HEADS + head] = vs;
                g_ald[gr * HEADS + head] = vd;
            }
        } else {  // OC == 2: thread's 4 cols span 2 heads
            float vs0 = acc[i][0]*asv.x + acc[i][1]*asv.y;
            float vd0 = acc[i][0]*adv.x + acc[i][1]*adv.y;
            float vs1 = acc[i][2]*asv.z + acc[i][3]*asv.w;
            float vd1 = acc[i][2]*adv.z + acc[i][3]*adv.w;
            if (ok) {
                g_als[gr * HEADS + cg * 2 + 0] = vs0;
                g_ald[gr * HEADS + cg * 2 + 0] = vd0;
                g_als[gr * HEADS + cg * 2 + 1] = vs1;
                g_ald[gr * HEADS + cg * 2 + 1] = vd1;
            }
        }
    }
}

// ---------------- fused softmax + aggregation (CSR gather, no atomics) --------
// SPLIT=2 lane groups per node walk disjoint halves of the edge range
// concurrently (doubles outstanding-miss parallelism on the latency chain),
// then combine acc/ssum with one shfl_xor(TPN) butterfly. Within each group,
// 8-edge batches preload indices, logits, and feature vectors before the FMA
// chain (MLP 8). Softmax shift skipped (shift-invariant, O(1) logits).
template<int OC>
__global__ __launch_bounds__(256) void k_agg(int N) {
    constexpr int F     = HEADS * OC;
    constexpr int V     = (OC >= 4) ? 4 : 2;
    constexpr int TPN   = F / V;          // channel lanes per group
    constexpr int LPH   = OC / V;         // lanes per head
    constexpr int SPLIT = 2;
    constexpr int TPG   = TPN * SPLIT;    // lanes per node (<= 32)
    constexpr int NPB   = 256 / TPG;
    static_assert(TPG <= 32, "node group must fit a warp");

    int node = blockIdx.x * NPB + threadIdx.x / TPG;
    if (node >= N) node = N - 1;          // clamp: duplicate compute, identical writes
    int local = threadIdx.x % TPG;
    int t     = local % TPN;
    int grp   = local / TPN;
    int head  = t / LPH;
    int wl    = threadIdx.x % 32;
    unsigned nmask = (TPG == 32) ? 0xffffffffu
                   : ((1u << TPG) - 1u) << (wl & ~(TPG - 1));

    int beg0 = g_off[node], end0 = g_off[node + 1];
    int mid  = beg0 + ((end0 - beg0) >> 1);
    int beg  = grp ? mid  : beg0;
    int end  = grp ? end0 : mid;

    float ald_d = g_ald[node * HEADS + head];

    float acc[V];
#pragma unroll
    for (int v = 0; v < V; v++) acc[v] = 0.f;
    float ssum = 0.f;

    int p = beg;
    for (; p + 8 <= end; p += 8) {
        int ss[8];
#pragma unroll
        for (int j = 0; j < 8; j++) ss[j] = g_csr_src[p + j];
        float al[8];
#pragma unroll
        for (int j = 0; j < 8; j++) al[j] = g_als[ss[j] * HEADS + head];
        if constexpr (V == 4) {
            float4 hv[8];
#pragma unroll
            for (int j = 0; j < 8; j++)
                hv[j] = *(const float4*)&g_h[ss[j] * F + t * V];
#pragma unroll
            for (int j = 0; j < 8; j++) {
                float ex = __expf(lrelu(al[j] + ald_d));
                ssum += ex;
                acc[0] += ex * hv[j].x; acc[1] += ex * hv[j].y;
                acc[2] += ex * hv[j].z; acc[3] += ex * hv[j].w;
            }
        } else {
            float2 hv[8];
#pragma unroll
            for (int j = 0; j < 8; j++)
                hv[j] = *(const float2*)&g_h[ss[j] * F + t * V];
#pragma unroll
            for (int j = 0; j < 8; j++) {
                float ex = __expf(lrelu(al[j] + ald_d));
                ssum += ex;
                acc[0] += ex * hv[j].x; acc[1] += ex * hv[j].y;
            }
        }
    }
    for (; p < end; p++) {
        int s = g_csr_src[p];
        float ex = __expf(lrelu(g_als[s * HEADS + head] + ald_d));
        ssum += ex;
        const float* hp = &g_h[s * F + t * V];
        if constexpr (V == 4) {
            float4 hv = *(const float4*)hp;
            acc[0] += ex * hv.x; acc[1] += ex * hv.y;
            acc[2] += ex * hv.z; acc[3] += ex * hv.w;
        } else {
            float2 hv = *(const float2*)hp;
            acc[0] += ex * hv.x; acc[1] += ex * hv.y;
        }
    }

    // combine the two edge-halves (lanes t and t+TPN hold the same channels)
    ssum += __shfl_xor_sync(nmask, ssum, TPN, 32);
#pragma unroll
    for (int v = 0; v < V; v++)
        acc[v] += __shfl_xor_sync(nmask, acc[v], TPN, 32);

    if (grp == 0) {
        float inv = 1.f / (ssum + 1e-16f);
        float* op = &g_o[node * F + t * V];
        if constexpr (V == 4)
            *(float4*)op = make_float4(acc[0] * inv, acc[1] * inv, acc[2] * inv, acc[3] * inv);
        else
            *(float2*)op = make_float2(acc[0] * inv, acc[1] * inv);
    }
}

// ---------------- pooling + fc -----------------------------------------------
__global__ void k_pool(const void* __restrict__ batch,
                       const float* __restrict__ b4, int N) {
    int n = blockIdx.x * blockDim.x + threadIdx.x;
    if (n >= N) return;
    int g = g_is64 ? (int)((const long long*)batch)[n]
                   : ((const int*)batch)[n];
#pragma unroll
    for (int j = 0; j < 8; j++) {
        float v = fmaxf(g_o[n * 8 + j] + b4[j], 0.f);
        atomicAdd(&g_psum[g * 8 + j], v);
    }
    atomicAdd(&g_pcnt[g], 1.f);
}

__global__ void k_fc(const float* __restrict__ Wfc,
                     const float* __restrict__ bfc, float* __restrict__ out) {
    int b = blockIdx.x, o = threadIdx.x;  // grid 64, block 32
    float c = fmaxf(g_pcnt[b], 1.f);
    float acc = bfc[o];
#pragma unroll
    for (int j = 0; j < 8; j++)
        acc += (g_psum[b * 8 + j] / c) * Wfc[j * 32 + o];
    out[b * 32 + o] = acc;
}

// ---------------- launch ------------------------------------------------------
extern "C" void kernel_launch(void* const* d_in, const int* in_sizes, int n_in,
                              void* d_out, int out_size) {
    const float* x    = (const float*)d_in[0];
    const void*  ei   = d_in[1];
    const void*  batch= d_in[2];
    const float* W1  = (const float*)d_in[3];
    const float* as1 = (const float*)d_in[4];
    const float* ad1 = (const float*)d_in[5];
    const float* b1  = (const float*)d_in[6];
    const float* W2  = (const float*)d_in[7];
    const float* as2 = (const float*)d_in[8];
    const float* ad2 = (const float*)d_in[9];
    const float* b2  = (const float*)d_in[10];
    const float* W3  = (const float*)d_in[11];
    const float* as3 = (const float*)d_in[12];
    const float* ad3 = (const float*)d_in[13];
    const float* b3  = (const float*)d_in[14];
    const float* W4  = (const float*)d_in[15];
    const float* as4 = (const float*)d_in[16];
    const float* ad4 = (const float*)d_in[17];
    const float* b4  = (const float*)d_in[18];
    const float* Wfc = (const float*)d_in[19];
    const float* bfc = (const float*)d_in[20];
    float* out = (float*)d_out;

    int N  = in_sizes[0] / 128;
    int E  = in_sizes[1] / 2;
    int EN = E + N;

    int nb = (N + 255) / 256;
    int eb = (EN + 255) / 256;
    int NB = (N + SCAN_CHUNK - 1) / SCAN_CHUNK;

    // ---- CSR build (once; reused by all 4 layers) ----
    k_detect<<<1, 256>>>((const unsigned*)ei, E);
    k_zero<<<nb, 256>>>(N);
    k_hist<<<eb, 256>>>(ei, E, N);
    k_scanA<<<NB, SCAN_CHUNK>>>(N);
    k_scanB<<<1, 256>>>(NB);
    k_scanC<<<nb, 256>>>(N);
    k_csr_scatter<<<eb, 256>>>(EN);

    // ---- layer 1 (in=x), F = 64, TPG = 32 ----
    k_gemm<128, 64, 32><<<(N + 31) / 32, 256>>>(x, 0, W1, nullptr, as1, ad1, N);
    k_agg<16><<<(N + 7) / 8, 256>>>(N);

    // ---- layer 2 (in = relu(g_o + b1)), F = 32, TPG = 16 ----
    k_gemm<64, 32, 128><<<(N + 127) / 128, 256>>>(nullptr, 1, W2, b1, as2, ad2, N);
    k_agg<8><<<(N + 15) / 16, 256>>>(N);

    // ---- layer 3, F = 16, TPG = 8 ----
    k_gemm<32, 16, 256><<<(N + 255) / 256, 256>>>(nullptr, 1, W3, b2, as3, ad3, N);
    k_agg<4><<<(N + 31) / 32, 256>>>(N);

    // ---- layer 4, F = 8, TPG = 8 ----
    k_gemm<16, 8, 512><<<(N + 511) / 512, 256>>>(nullptr, 1, W4, b3, as4, ad4, N);
    k_agg<2><<<(N + 31) / 32, 256>>>(N);

    // ---- global mean pool (relu(g_o + b4)) + fc ----
    k_pool<<<nb, 256>>>(batch, b4, N);
    k_fc<<<64, 32>>>(Wfc, bfc, out);
}

// round 9
// speedup vs baseline: 1.1502x; 1.0797x over previous
#include <cuda_runtime.h>

#define HEADS 4
#define NEG_SLOPE 0.2f

static const int N_CAP  = 100000;
static const int EN_CAP = 1700000;
static const int SCAN_CHUNK = 512;

// ---------------- scratch (static device globals; no allocation) -------------
__device__ float g_h  [N_CAP * 64];   // transformed features h = in @ W   [N, F]
__device__ float g_o  [N_CAP * 64];   // aggregated output (next layer in) [N, F]
__device__ float g_als[N_CAP * HEADS];
__device__ float g_ald[N_CAP * HEADS];
__device__ int   g_src[EN_CAP];
__device__ int   g_dst[EN_CAP];
__device__ int   g_csr_src[EN_CAP];
__device__ int   g_deg[N_CAP];
__device__ int   g_inc[N_CAP];
__device__ int   g_off[N_CAP + 1];
__device__ int   g_cursor[N_CAP];
__device__ int   g_bsum[256];
__device__ int   g_boff[256];
__device__ float g_psum[64 * 8];
__device__ float g_pcnt[64];
__device__ int   g_is64;

// ---------------- helpers ----------------------------------------------------
__device__ __forceinline__ float lrelu(float x) { return x > 0.f ? x : NEG_SLOPE * x; }

// ---------------- index-width detection --------------------------------------
__global__ void k_detect(const unsigned* __restrict__ w, int pairs) {
    __shared__ int any;
    if (threadIdx.x == 0) any = 0;
    __syncthreads();
    int lim = pairs < 4096 ? pairs : 4096;
    int local = 0;
    for (int i = threadIdx.x; i < lim; i += blockDim.x)
        if (w[2 * i + 1] != 0u) local = 1;
    if (local) atomicExch(&any, 1);
    __syncthreads();
    if (threadIdx.x == 0) g_is64 = (any == 0) ? 1 : 0;
}

// ---------------- zero transient state ---------------------------------------
__global__ void k_zero(int N) {
    int i = blockIdx.x * blockDim.x + threadIdx.x;
    if (i < N) { g_deg[i] = 0; g_cursor[i] = 0; }
    if (i < 512) g_psum[i] = 0.f;
    if (i < 64)  g_pcnt[i] = 0.f;
}

// ---------------- decode edges + dst histogram --------------------------------
__global__ void k_hist(const void* __restrict__ ei, int E, int N) {
    int i = blockIdx.x * blockDim.x + threadIdx.x;
    int EN = E + N;
    if (i >= EN) return;
    int s, d;
    if (i < E) {
        if (g_is64) {
            const long long* p = (const long long*)ei;
            s = (int)p[i]; d = (int)p[E + i];
        } else {
            const int* p = (const int*)ei;
            s = p[i]; d = p[E + i];
        }
    } else {             // self-loops appended (PyG GATConv behavior)
        s = d = i - E;
    }
    g_src[i] = s;
    g_dst[i] = d;
    atomicAdd(&g_deg[d], 1);
}

// ---------------- 3-phase exclusive scan of g_deg -> g_off --------------------
__global__ __launch_bounds__(SCAN_CHUNK) void k_scanA(int N) {
    __shared__ int sh[SCAN_CHUNK];
    int i = blockIdx.x * SCAN_CHUNK + threadIdx.x;
    int v = (i < N) ? g_deg[i] : 0;
    sh[threadIdx.x] = v;
    __syncthreads();
    for (int off = 1; off < SCAN_CHUNK; off <<= 1) {
        int t = (threadIdx.x >= off) ? sh[threadIdx.x - off] : 0;
        __syncthreads();
        sh[threadIdx.x] += t;
        __syncthreads();
    }
    if (i < N) g_inc[i] = sh[threadIdx.x];
    if (threadIdx.x == SCAN_CHUNK - 1) g_bsum[blockIdx.x] = sh[SCAN_CHUNK - 1];
}

__global__ __launch_bounds__(256) void k_scanB(int NB) {
    __shared__ int sh[256];
    int t = threadIdx.x;
    int v = (t < NB) ? g_bsum[t] : 0;
    sh[t] = v;
    __syncthreads();
    for (int off = 1; off < 256; off <<= 1) {
        int tv = (t >= off) ? sh[t - off] : 0;
        __syncthreads();
        sh[t] += tv;
        __syncthreads();
    }
    if (t < NB) g_boff[t] = sh[t] - v;   // exclusive
}

__global__ void k_scanC(int N) {
    int i = blockIdx.x * blockDim.x + threadIdx.x;
    if (i >= N) return;
    int b = i / SCAN_CHUNK;
    int inc = g_inc[i] + g_boff[b];
    g_off[i] = inc - g_deg[i];
    if (i == N - 1) g_off[N] = inc;
}

// ---------------- scatter edges into CSR order --------------------------------
__global__ void k_csr_scatter(int EN) {
    int i = blockIdx.x * blockDim.x + threadIdx.x;
    if (i >= EN) return;
    int d = g_dst[i];
    int pos = g_off[d] + atomicAdd(&g_cursor[d], 1);
    g_csr_src[pos] = g_src[i];
}

// ---------------- GEMM + fused attention-logit epilogue (round-6 proven) -----
// g_h = act(in [+bias]) @ W ; g_als/g_ald = per-head dot(h_row, a_src/a_dst).
template<int K, int M, int ROWS>
__global__ __launch_bounds__(256) void k_gemm(
    const float* __restrict__ in_ext, int use_int,
    const float* __restrict__ W, const float* __restrict__ bias,
    const float* __restrict__ a_src, const float* __restrict__ a_dst, int N)
{
    constexpr int CG  = M / 4;
    constexpr int RG  = 256 / CG;
    constexpr int RPT = ROWS / RG;
    constexpr int OC  = M / HEADS;
    constexpr int RED = (OC >= 4) ? OC / 4 : 1;
    constexpr int KP  = (K == 128) ? K : (K + 1);
    __shared__ float sW[K * M];
    __shared__ float sIn[ROWS * KP];

    const float* in = use_int ? g_o : in_ext;
    int r0 = blockIdx.x * ROWS;

    for (int i = threadIdx.x; i < K * M; i += 256) sW[i] = W[i];
    for (int i = threadIdx.x; i < ROWS * K; i += 256) {
        int r = i / K, k = i - r * K;
        int gr = r0 + r;
        float v = 0.f;
        if (gr < N) {
            v = in[gr * K + k];
            if (bias) { v += bias[k]; v = fmaxf(v, 0.f); }
        }
        sIn[r * KP + k] = v;
    }
    __syncthreads();

    int cg = threadIdx.x % CG;
    int rg = threadIdx.x / CG;
    float acc[RPT][4];
#pragma unroll
    for (int i = 0; i < RPT; i++)
        acc[i][0] = acc[i][1] = acc[i][2] = acc[i][3] = 0.f;

#pragma unroll 8
    for (int k = 0; k < K; k++) {
        float w0 = sW[k * M + cg * 4 + 0];
        float w1 = sW[k * M + cg * 4 + 1];
        float w2 = sW[k * M + cg * 4 + 2];
        float w3 = sW[k * M + cg * 4 + 3];
#pragma unroll
        for (int i = 0; i < RPT; i++) {
            float a = sIn[(rg * RPT + i) * KP + k];
            acc[i][0] += a * w0; acc[i][1] += a * w1;
            acc[i][2] += a * w2; acc[i][3] += a * w3;
        }
    }

    float4 asv = *(const float4*)&a_src[cg * 4];
    float4 adv = *(const float4*)&a_dst[cg * 4];

#pragma unroll
    for (int i = 0; i < RPT; i++) {
        int gr = r0 + rg * RPT + i;
        bool ok = (gr < N);
        if (ok) {
            float4 v = make_float4(acc[i][0], acc[i][1], acc[i][2], acc[i][3]);
            *(float4*)&g_h[gr * M + cg * 4] = v;
        }
        if constexpr (OC >= 4) {
            float vs = acc[i][0]*asv.x + acc[i][1]*asv.y + acc[i][2]*asv.z + acc[i][3]*asv.w;
            float vd = acc[i][0]*adv.x + acc[i][1]*adv.y + acc[i][2]*adv.z + acc[i][3]*adv.w;
#pragma unroll
            for (int o = 1; o < RED; o <<= 1) {
                vs += __shfl_xor_sync(0xffffffffu, vs, o, 32);
                vd += __shfl_xor_sync(0xffffffffu, vd, o, 32);
            }
            if (ok && (cg % RED) == 0) {
                int head = cg / RED;
                g_als[gr * HEADS + head] = vs;
                g_ald[gr * HEADS + head] = vd;
            }
        } else {  // OC == 2: thread's 4 cols span 2 heads
            float vs0 = acc[i][0]*asv.x + acc[i][1]*asv.y;
            float vd0 = acc[i][0]*adv.x + acc[i][1]*adv.y;
            float vs1 = acc[i][2]*asv.z + acc[i][3]*asv.w;
            float vd1 = acc[i][2]*adv.z + acc[i][3]*adv.w;
            if (ok) {
                g_als[gr * HEADS + cg * 2 + 0] = vs0;
                g_ald[gr * HEADS + cg * 2 + 0] = vd0;
                g_als[gr * HEADS + cg * 2 + 1] = vs1;
                g_ald[gr * HEADS + cg * 2 + 1] = vd1;
            }
        }
    }
}

// ---------------- fused softmax + aggregation (round-6 proven) ----------------
// TPN = F/V threads per node. 8-edge batches preload indices and logits; the
// feature float4 is consumed immediately (register-lean). Softmax shift
// skipped (shift-invariant, O(1) logits).
template<int OC>
__global__ __launch_bounds__(256) void k_agg(int N) {
    constexpr int F   = HEADS * OC;
    constexpr int V   = (OC >= 4) ? 4 : 2;
    constexpr int TPN = F / V;
    constexpr int LPH = OC / V;        // lanes per head
    constexpr int NPB = 256 / TPN;
    int node = blockIdx.x * NPB + threadIdx.x / TPN;
    if (node >= N) node = N - 1;       // clamp: duplicate compute, identical writes
    int t    = threadIdx.x % TPN;
    int head = t / LPH;

    int beg = g_off[node], end = g_off[node + 1];
    float ald_d = g_ald[node * HEADS + head];

    float acc[V];
#pragma unroll
    for (int v = 0; v < V; v++) acc[v] = 0.f;
    float ssum = 0.f;

    int p = beg;
    for (; p + 8 <= end; p += 8) {
        int ss[8];
#pragma unroll
        for (int j = 0; j < 8; j++) ss[j] = g_csr_src[p + j];
        float al[8];
#pragma unroll
        for (int j = 0; j < 8; j++) al[j] = g_als[ss[j] * HEADS + head];
#pragma unroll
        for (int j = 0; j < 8; j++) {
            float ex = __expf(lrelu(al[j] + ald_d));
            ssum += ex;
            const float* hp = &g_h[ss[j] * F + t * V];
            if constexpr (V == 4) {
                float4 hv = *(const float4*)hp;
                acc[0] += ex * hv.x; acc[1] += ex * hv.y;
                acc[2] += ex * hv.z; acc[3] += ex * hv.w;
            } else {
                float2 hv = *(const float2*)hp;
                acc[0] += ex * hv.x; acc[1] += ex * hv.y;
            }
        }
    }
    for (; p < end; p++) {
        int s = g_csr_src[p];
        float ex = __expf(lrelu(g_als[s * HEADS + head] + ald_d));
        ssum += ex;
        const float* hp = &g_h[s * F + t * V];
        if constexpr (V == 4) {
            float4 hv = *(const float4*)hp;
            acc[0] += ex * hv.x; acc[1] += ex * hv.y;
            acc[2] += ex * hv.z; acc[3] += ex * hv.w;
        } else {
            float2 hv = *(const float2*)hp;
            acc[0] += ex * hv.x; acc[1] += ex * hv.y;
        }
    }

    float inv = 1.f / (ssum + 1e-16f);
    float* op = &g_o[node * F + t * V];
    if constexpr (V == 4)
        *(float4*)op = make_float4(acc[0] * inv, acc[1] * inv, acc[2] * inv, acc[3] * inv);
    else
        *(float2*)op = make_float2(acc[0] * inv, acc[1] * inv);
}

// ---------------- pooling + fc -----------------------------------------------
__global__ void k_pool(const void* __restrict__ batch,
                       const float* __restrict__ b4, int N) {
    int n = blockIdx.x * blockDim.x + threadIdx.x;
    if (n >= N) return;
    int g = g_is64 ? (int)((const long long*)batch)[n]
                   : ((const int*)batch)[n];
#pragma unroll
    for (int j = 0; j < 8; j++) {
        float v = fmaxf(g_o[n * 8 + j] + b4[j], 0.f);
        atomicAdd(&g_psum[g * 8 + j], v);
    }
    atomicAdd(&g_pcnt[g], 1.f);
}

__global__ void k_fc(const float* __restrict__ Wfc,
                     const float* __restrict__ bfc, float* __restrict__ out) {
    int b = blockIdx.x, o = threadIdx.x;  // grid 64, block 32
    float c = fmaxf(g_pcnt[b], 1.f);
    float acc = bfc[o];
#pragma unroll
    for (int j = 0; j < 8; j++)
        acc += (g_psum[b * 8 + j] / c) * Wfc[j * 32 + o];
    out[b * 32 + o] = acc;
}

// ---------------- launch ------------------------------------------------------
extern "C" void kernel_launch(void* const* d_in, const int* in_sizes, int n_in,
                              void* d_out, int out_size) {
    const float* x    = (const float*)d_in[0];
    const void*  ei   = d_in[1];
    const void*  batch= d_in[2];
    const float* W1  = (const float*)d_in[3];
    const float* as1 = (const float*)d_in[4];
    const float* ad1 = (const float*)d_in[5];
    const float* b1  = (const float*)d_in[6];
    const float* W2  = (const float*)d_in[7];
    const float* as2 = (const float*)d_in[8];
    const float* ad2 = (const float*)d_in[9];
    const float* b2  = (const float*)d_in[10];
    const float* W3  = (const float*)d_in[11];
    const float* as3 = (const float*)d_in[12];
    const float* ad3 = (const float*)d_in[13];
    const float* b3  = (const float*)d_in[14];
    const float* W4  = (const float*)d_in[15];
    const float* as4 = (const float*)d_in[16];
    const float* ad4 = (const float*)d_in[17];
    const float* b4  = (const float*)d_in[18];
    const float* Wfc = (const float*)d_in[19];
    const float* bfc = (const float*)d_in[20];
    float* out = (float*)d_out;

    int N  = in_sizes[0] / 128;
    int E  = in_sizes[1] / 2;
    int EN = E + N;

    int nb = (N + 255) / 256;
    int eb = (EN + 255) / 256;
    int NB = (N + SCAN_CHUNK - 1) / SCAN_CHUNK;

    // Side stream + fork/join events, created once on the FIRST call (the
    // correctness run, which is NOT captured) — nothing is created inside the
    // graph. No device memory is allocated by stream/event creation.
    static cudaStream_t s2 = nullptr;
    static cudaEvent_t evFork = nullptr, evJoin = nullptr;
    if (s2 == nullptr) {
        cudaStreamCreateWithFlags(&s2, cudaStreamNonBlocking);
        cudaEventCreateWithFlags(&evFork, cudaEventDisableTiming);
        cudaEventCreateWithFlags(&evJoin, cudaEventDisableTiming);
    }

    // ---- fork: CSR build on s2, GEMM1 on the main stream, concurrently ----
    cudaEventRecord(evFork, 0);
    cudaStreamWaitEvent(s2, evFork, 0);

    k_detect<<<1, 256, 0, s2>>>((const unsigned*)ei, E);
    k_zero<<<nb, 256, 0, s2>>>(N);
    k_hist<<<eb, 256, 0, s2>>>(ei, E, N);
    k_scanA<<<NB, SCAN_CHUNK, 0, s2>>>(N);
    k_scanB<<<1, 256, 0, s2>>>(NB);
    k_scanC<<<nb, 256, 0, s2>>>(N);
    k_csr_scatter<<<eb, 256, 0, s2>>>(EN);

    // layer-1 GEMM runs concurrently on the main stream (depends only on x/W1)
    k_gemm<128, 64, 32><<<(N + 31) / 32, 256>>>(x, 0, W1, nullptr, as1, ad1, N);

    // ---- join: aggregation needs both the CSR and GEMM1 results ----
    cudaEventRecord(evJoin, s2);
    cudaStreamWaitEvent(0, evJoin, 0);

    // ---- layer 1 (F = 64) ----
    k_agg<16><<<(N + 15) / 16, 256>>>(N);

    // ---- layer 2 (in = relu(g_o + b1)), F = 32 ----
    k_gemm<64, 32, 128><<<(N + 127) / 128, 256>>>(nullptr, 1, W2, b1, as2, ad2, N);
    k_agg<8><<<(N + 31) / 32, 256>>>(N);

    // ---- layer 3, F = 16 ----
    k_gemm<32, 16, 256><<<(N + 255) / 256, 256>>>(nullptr, 1, W3, b2, as3, ad3, N);
    k_agg<4><<<(N + 63) / 64, 256>>>(N);

    // ---- layer 4, F = 8 ----
    k_gemm<16, 8, 512><<<(N + 511) / 512, 256>>>(nullptr, 1, W4, b3, as4, ad4, N);
    k_agg<2><<<(N + 63) / 64, 256>>>(N);

    // ---- global mean pool (relu(g_o + b4)) + fc ----
    k_pool<<<nb, 256>>>(batch, b4, N);
    k_fc<<<64, 32>>>(Wfc, bfc, out);
}